// round 16
// baseline (speedup 1.0000x reference)
#include <cuda_runtime.h>

// ComposeTransform: out[b] = trilinear(disp1[b], grid + disp2[b]) + disp2[b]
// vol per batch: [D,H,W,3], D=160, H=192, W=160, batch=2.
// R14/R15 skeleton (thread=(voxel,channel), AoS gathers, __stcs stores) with
// EIGHT sequential elements per thread: 14,400 blocks (~12 waves) -> minimal
// block drain/refill churn; each eighth keeps sequential block->address
// locality (8 thin concurrent slabs, trivially L2-resident).

#define DD 160
#define HH 192
#define WW 160
#define VOX (DD * HH * WW)
#define NELEM (2 * VOX * 3)     // 29,491,200
#define SEG (NELEM / 8)         // 3,686,400 = 256 * 14,400

__device__ __forceinline__ float compose_one(const float* __restrict__ d1,
                                             const float* __restrict__ d2,
                                             int t)
{
    int v  = t / 3;          // voxel index (global, includes batch)
    int ch = t - v * 3;      // channel 0..2

    int b = v / VOX;
    int r = v - b * VOX;
    int x = r / (HH * WW);
    int rem = r - x * (HH * WW);
    int y = rem / WW;
    int z = rem - y * WW;

    const float* pd2 = d2 + (size_t)v * 3;
    float dx = __ldg(pd2 + 0);
    float dy = __ldg(pd2 + 1);
    float dz = __ldg(pd2 + 2);

    float lx = (float)x + dx;
    float ly = (float)y + dy;
    float lz = (float)z + dz;

    float fx = floorf(lx);
    float fy = floorf(ly);
    float fz = floorf(lz);

    // clipped floor / ceil corners (reference semantics)
    float i0x = fminf(fmaxf(fx, 0.0f), (float)(DD - 1));
    float i0y = fminf(fmaxf(fy, 0.0f), (float)(HH - 1));
    float i0z = fminf(fmaxf(fz, 0.0f), (float)(WW - 1));
    float i1x = fminf(fmaxf(fx + 1.0f, 0.0f), (float)(DD - 1));
    float i1y = fminf(fmaxf(fy + 1.0f, 0.0f), (float)(HH - 1));
    float i1z = fminf(fmaxf(fz + 1.0f, 0.0f), (float)(WW - 1));

    // weight attached to floor corner = clip(ceil_clipped - loc, 0, 1)
    float wfx = fminf(fmaxf(i1x - lx, 0.0f), 1.0f);
    float wfy = fminf(fmaxf(i1y - ly, 0.0f), 1.0f);
    float wfz = fminf(fmaxf(i1z - lz, 0.0f), 1.0f);
    float wcx = 1.0f - wfx;
    float wcy = 1.0f - wfy;
    float wcz = 1.0f - wfz;

    int ix0 = (int)i0x, iy0 = (int)i0y, iz0 = (int)i0z;
    int ix1 = (int)i1x, iy1 = (int)i1y, iz1 = (int)i1z;

    const float* vbase = d1 + (size_t)b * (size_t)(VOX * 3) + ch;

    int row00 = (ix0 * HH + iy0) * (WW * 3);
    int row01 = (ix0 * HH + iy1) * (WW * 3);
    int row10 = (ix1 * HH + iy0) * (WW * 3);
    int row11 = (ix1 * HH + iy1) * (WW * 3);
    int z0 = iz0 * 3;
    int z1 = iz1 * 3;

    float w00z0 = wfx * wfy * wfz;
    float w00z1 = wfx * wfy * wcz;
    float w01z0 = wfx * wcy * wfz;
    float w01z1 = wfx * wcy * wcz;
    float w10z0 = wcx * wfy * wfz;
    float w10z1 = wcx * wfy * wcz;
    float w11z0 = wcx * wcy * wfz;
    float w11z1 = wcx * wcy * wcz;

    float g0 = __ldg(vbase + (row00 + z0));
    float g1 = __ldg(vbase + (row00 + z1));
    float g2 = __ldg(vbase + (row01 + z0));
    float g3 = __ldg(vbase + (row01 + z1));
    float g4 = __ldg(vbase + (row10 + z0));
    float g5 = __ldg(vbase + (row10 + z1));
    float g6 = __ldg(vbase + (row11 + z0));
    float g7 = __ldg(vbase + (row11 + z1));

    float q0 = fmaf(w00z1, g1, w00z0 * g0);
    float q1 = fmaf(w01z1, g3, w01z0 * g2);
    float q2 = fmaf(w10z1, g5, w10z0 * g4);
    float q3 = fmaf(w11z1, g7, w11z0 * g6);
    float acc = (q0 + q1) + (q2 + q3);

    float d2c = (ch == 0) ? dx : ((ch == 1) ? dy : dz);
    return acc + d2c;
}

__global__ __launch_bounds__(256, 8)
void compose_kernel(const float* __restrict__ d1,
                    const float* __restrict__ d2,
                    float* __restrict__ out)
{
    int t = blockIdx.x * blockDim.x + threadIdx.x;   // 0 .. SEG-1, exact grid

#pragma unroll
    for (int s = 0; s < 8; s++) {
        int ts = t + s * SEG;
        __stcs(out + ts, compose_one(d1, d2, ts));
    }
}

extern "C" void kernel_launch(void* const* d_in, const int* in_sizes, int n_in,
                              void* d_out, int out_size) {
    const float* d1 = (const float*)d_in[0];
    const float* d2 = (const float*)d_in[1];
    float* out = (float*)d_out;
    // SEG = 3,686,400 = 256 * 14,400 exactly
    compose_kernel<<<SEG / 256, 256>>>(d1, d2, out);
}

// round 17
// speedup vs baseline: 1.0117x; 1.0117x over previous
#include <cuda_runtime.h>

// ComposeTransform: out[b] = trilinear(disp1[b], grid + disp2[b]) + disp2[b]
// vol per batch: [D,H,W,3], D=160, H=192, W=160, batch=2.
// R15 4-segment skeleton, but using the algebraic structure of the segments:
// QTR = VOX/2 voxels, so segment s differs only by b=s/2 and x+=80*(s&1).
// Coordinates/divides computed ONCE per thread; per segment only the x/b
// swap. All four d2 addresses are known up-front -> ptxas can overlap the
// next segment's loads with the current segment's FMA tail.

#define DD 160
#define HH 192
#define WW 160
#define VOX (DD * HH * WW)
#define NELEM (2 * VOX * 3)     // 29,491,200
#define QTR (NELEM / 4)         // 7,372,800 = 256 * 28,800; = VOX/2 voxels
#define HVOX (VOX / 2)          // 2,457,600 voxels per segment

__device__ __forceinline__ float compose_core(const float* __restrict__ d1,
                                              const float* __restrict__ d2,
                                              int vs,   // global voxel index (incl. batch)
                                              int b, int x, int y, int z, int ch,
                                              float* d2c_out)
{
    const float* pd2 = d2 + (size_t)vs * 3;
    float dx = __ldg(pd2 + 0);
    float dy = __ldg(pd2 + 1);
    float dz = __ldg(pd2 + 2);

    float lx = (float)x + dx;
    float ly = (float)y + dy;
    float lz = (float)z + dz;

    float fx = floorf(lx);
    float fy = floorf(ly);
    float fz = floorf(lz);

    // clipped floor / ceil corners (reference semantics)
    float i0x = fminf(fmaxf(fx, 0.0f), (float)(DD - 1));
    float i0y = fminf(fmaxf(fy, 0.0f), (float)(HH - 1));
    float i0z = fminf(fmaxf(fz, 0.0f), (float)(WW - 1));
    float i1x = fminf(fmaxf(fx + 1.0f, 0.0f), (float)(DD - 1));
    float i1y = fminf(fmaxf(fy + 1.0f, 0.0f), (float)(HH - 1));
    float i1z = fminf(fmaxf(fz + 1.0f, 0.0f), (float)(WW - 1));

    // weight attached to floor corner = clip(ceil_clipped - loc, 0, 1)
    float wfx = fminf(fmaxf(i1x - lx, 0.0f), 1.0f);
    float wfy = fminf(fmaxf(i1y - ly, 0.0f), 1.0f);
    float wfz = fminf(fmaxf(i1z - lz, 0.0f), 1.0f);
    float wcx = 1.0f - wfx;
    float wcy = 1.0f - wfy;
    float wcz = 1.0f - wfz;

    int ix0 = (int)i0x, iy0 = (int)i0y, iz0 = (int)i0z;
    int ix1 = (int)i1x, iy1 = (int)i1y, iz1 = (int)i1z;

    const float* vbase = d1 + (size_t)b * (size_t)(VOX * 3) + ch;

    int row00 = (ix0 * HH + iy0) * (WW * 3);
    int row01 = (ix0 * HH + iy1) * (WW * 3);
    int row10 = (ix1 * HH + iy0) * (WW * 3);
    int row11 = (ix1 * HH + iy1) * (WW * 3);
    int z0 = iz0 * 3;
    int z1 = iz1 * 3;

    float w00z0 = wfx * wfy * wfz;
    float w00z1 = wfx * wfy * wcz;
    float w01z0 = wfx * wcy * wfz;
    float w01z1 = wfx * wcy * wcz;
    float w10z0 = wcx * wfy * wfz;
    float w10z1 = wcx * wfy * wcz;
    float w11z0 = wcx * wcy * wfz;
    float w11z1 = wcx * wcy * wcz;

    float g0 = __ldg(vbase + (row00 + z0));
    float g1 = __ldg(vbase + (row00 + z1));
    float g2 = __ldg(vbase + (row01 + z0));
    float g3 = __ldg(vbase + (row01 + z1));
    float g4 = __ldg(vbase + (row10 + z0));
    float g5 = __ldg(vbase + (row10 + z1));
    float g6 = __ldg(vbase + (row11 + z0));
    float g7 = __ldg(vbase + (row11 + z1));

    float q0 = fmaf(w00z1, g1, w00z0 * g0);
    float q1 = fmaf(w01z1, g3, w01z0 * g2);
    float q2 = fmaf(w10z1, g5, w10z0 * g4);
    float q3 = fmaf(w11z1, g7, w11z0 * g6);
    float acc = (q0 + q1) + (q2 + q3);

    *d2c_out = (ch == 0) ? dx : ((ch == 1) ? dy : dz);
    return acc;
}

__global__ __launch_bounds__(256, 8)
void compose_kernel(const float* __restrict__ d1,
                    const float* __restrict__ d2,
                    float* __restrict__ out)
{
    int t = blockIdx.x * blockDim.x + threadIdx.x;   // 0 .. QTR-1, exact grid

    // decode ONCE: segment-0 element lives in batch 0, x in [0,80)
    int v  = t / 3;           // voxel in [0, HVOX)
    int ch = t - v * 3;
    int x0 = v / (HH * WW);   // 0..79
    int rem = v - x0 * (HH * WW);
    int y = rem / WW;
    int z = rem - y * WW;

    // segment s: b = s>>1, x = x0 + 80*(s&1), voxel = v + s*HVOX
    float d2c, acc;

    acc = compose_core(d1, d2, v,            0, x0,      y, z, ch, &d2c);
    __stcs(out + t, acc + d2c);

    acc = compose_core(d1, d2, v + HVOX,     0, x0 + 80, y, z, ch, &d2c);
    __stcs(out + t + QTR, acc + d2c);

    acc = compose_core(d1, d2, v + 2 * HVOX, 1, x0,      y, z, ch, &d2c);
    __stcs(out + t + 2 * QTR, acc + d2c);

    acc = compose_core(d1, d2, v + 3 * HVOX, 1, x0 + 80, y, z, ch, &d2c);
    __stcs(out + t + 3 * QTR, acc + d2c);
}

extern "C" void kernel_launch(void* const* d_in, const int* in_sizes, int n_in,
                              void* d_out, int out_size) {
    const float* d1 = (const float*)d_in[0];
    const float* d2 = (const float*)d_in[1];
    float* out = (float*)d_out;
    // QTR = 7,372,800 = 256 * 28,800 exactly
    compose_kernel<<<QTR / 256, 256>>>(d1, d2, out);
}